// round 4
// baseline (speedup 1.0000x reference)
#include <cuda_runtime.h>
#include <math.h>

#define NN 100000
#define EE 1600000

// ---------------- device scratch (allocation-free: __device__ globals) ------
__device__ int   g_eidx[2 * EE];   // converted edge_index (int32), [src | dst]
__device__ int   g_is64;
__device__ int   g_deg[NN];
__device__ int   g_off[NN + 1];
__device__ int   g_cursor[NN];
__device__ int   g_srcs[EE];
__device__ float g_agg[NN * 64];
__device__ float g_h1[NN * 128];
__device__ float g_hr[NN * 64];
__device__ float g_h2pre[NN * 64];
__device__ float g_h2[NN * 64];
__device__ float g_w[NN];
__device__ float g_bmax[12500];
__device__ float g_pool[64];
__device__ float g_Z;
__device__ float g_M;

// ---------------- zero-init (graph memset nodes can't target __device__ globals)
__global__ __launch_bounds__(256) void init_kernel() {
    int i = blockIdx.x * blockDim.x + threadIdx.x;
    if (i < NN) { g_deg[i] = 0; g_cursor[i] = 0; }
    if (i < 64) g_pool[i] = 0.f;
    if (i == 0) g_Z = 0.f;
}

// ---------------- edge_index dtype detection + conversion -------------------
// If the buffer is really int64, sampled words are all in [0, NN).
// If it is int32 misread as int64, words pack two indices -> huge values.
__global__ __launch_bounds__(32) void detect_kernel(const void* ei) {
    const long long* p = (const long long*)ei;
    int lane = threadIdx.x;
    long long v = p[lane * 7];
    bool ok = (v >= 0 && v < NN);
    unsigned m = __ballot_sync(0xffffffffu, ok);
    if (lane == 0) g_is64 = (m == 0xffffffffu) ? 1 : 0;
}

__global__ __launch_bounds__(256) void convert_kernel(const void* ei) {
    int e = blockIdx.x * blockDim.x + threadIdx.x;
    if (e >= 2 * EE) return;
    int v;
    if (g_is64) v = (int)((const long long*)ei)[e];
    else        v = ((const int*)ei)[e];
    g_eidx[e] = v;
}

// ---------------- CSR build --------------------------------------------------
__global__ __launch_bounds__(256) void hist_kernel() {
    int e = blockIdx.x * blockDim.x + threadIdx.x;
    if (e < EE) {
        int d = g_eidx[EE + e];
        atomicAdd(&g_deg[d], 1);
    }
}

__global__ __launch_bounds__(1024) void scan_kernel() {
    __shared__ int ss[1024];
    const int t = threadIdx.x;
    const int CHUNK = 98;              // 1024*98 = 100352 >= NN
    int base = t * CHUNK;
    int local = 0;
#pragma unroll 1
    for (int i = 0; i < CHUNK; i++) {
        int idx = base + i;
        if (idx < NN) local += g_deg[idx];
    }
    ss[t] = local;
    __syncthreads();
#pragma unroll 1
    for (int off = 1; off < 1024; off <<= 1) {
        int tmp = (t >= off) ? ss[t - off] : 0;
        __syncthreads();
        ss[t] += tmp;
        __syncthreads();
    }
    int run = (t > 0) ? ss[t - 1] : 0;
#pragma unroll 1
    for (int i = 0; i < CHUNK; i++) {
        int idx = base + i;
        if (idx < NN) {
            g_off[idx] = run;
            run += g_deg[idx];
        }
    }
    if (t == 1023) g_off[NN] = ss[1023];
}

__global__ __launch_bounds__(256) void scatter_kernel() {
    int e = blockIdx.x * blockDim.x + threadIdx.x;
    if (e < EE) {
        int s = g_eidx[e];
        int d = g_eidx[EE + e];
        int pos = g_off[d] + atomicAdd(&g_cursor[d], 1);
        g_srcs[pos] = s;
    }
}

// ---------------- mean aggregation (warp per node, 64-dim rows) -------------
__global__ __launch_bounds__(256) void agg_kernel(
    const float* __restrict__ feat, float* __restrict__ out)
{
    int w = (blockIdx.x * blockDim.x + threadIdx.x) >> 5;
    int lane = threadIdx.x & 31;
    if (w >= NN) return;
    int beg = g_off[w];
    int d = g_deg[w];
    int end = beg + d;
    const float2* __restrict__ F = reinterpret_cast<const float2*>(feat);
    float ax = 0.f, ay = 0.f;
    int j = beg;
    for (; j + 1 < end; j += 2) {
        int s0 = __ldg(&g_srcs[j]);
        int s1 = __ldg(&g_srcs[j + 1]);
        float2 v0 = F[s0 * 32 + lane];
        float2 v1 = F[s1 * 32 + lane];
        ax += v0.x + v1.x;
        ay += v0.y + v1.y;
    }
    if (j < end) {
        int s = __ldg(&g_srcs[j]);
        float2 v = F[s * 32 + lane];
        ax += v.x; ay += v.y;
    }
    float inv = 1.0f / fmaxf((float)d, 1.0f);
    float2 o; o.x = ax * inv; o.y = ay * inv;
    reinterpret_cast<float2*>(out)[w * 32 + lane] = o;
}

// ---------------- GEMM1: h1 = relu([agg|x] @ [W1_l;W1_r] + b1) --------------
// block: 64 rows x 128 cols, 256 threads, 4x8 per-thread tile
#define SMEM_GEMM ((64 * 132 + 128 * 128) * 4)

__global__ __launch_bounds__(256) void gemm1_kernel(
    const float* __restrict__ agg, const float* __restrict__ x,
    const float* __restrict__ W1l, const float* __restrict__ W1r,
    const float* __restrict__ b1, float* __restrict__ h1)
{
    extern __shared__ float sm[];
    float* sA = sm;                 // [64][132]
    float* sB = sm + 64 * 132;      // [128][128]
    const int tid = threadIdx.x;
    const int r0 = blockIdx.x * 64;

    for (int f = tid; f < 128 * 128; f += 256) {
        int k = f >> 7, j = f & 127;
        sB[f] = (k < 64) ? __ldg(&W1l[k * 128 + j]) : __ldg(&W1r[(k - 64) * 128 + j]);
    }
    for (int f = tid; f < 64 * 128; f += 256) {
        int r = f >> 7, k = f & 127;
        int row = r0 + r;
        float v = 0.f;
        if (row < NN) v = (k < 64) ? agg[row * 64 + k] : x[row * 64 + (k - 64)];
        sA[r * 132 + k] = v;
    }
    __syncthreads();

    const int tx = tid & 15, ty = tid >> 4;
    float acc[4][8];
#pragma unroll
    for (int i = 0; i < 4; i++)
#pragma unroll
        for (int j = 0; j < 8; j++) acc[i][j] = 0.f;

    const float* pA = sA + (ty * 4) * 132;
    const float* pB = sB + tx * 8;
#pragma unroll 8
    for (int k = 0; k < 128; k++) {
        float av[4];
        av[0] = pA[k];
        av[1] = pA[132 + k];
        av[2] = pA[264 + k];
        av[3] = pA[396 + k];
        float4 bl = *reinterpret_cast<const float4*>(pB + k * 128);
        float4 bh = *reinterpret_cast<const float4*>(pB + k * 128 + 4);
        float bv[8] = {bl.x, bl.y, bl.z, bl.w, bh.x, bh.y, bh.z, bh.w};
#pragma unroll
        for (int i = 0; i < 4; i++)
#pragma unroll
            for (int j = 0; j < 8; j++)
                acc[i][j] += av[i] * bv[j];
    }

    float bias[8];
#pragma unroll
    for (int j = 0; j < 8; j++) bias[j] = __ldg(&b1[tx * 8 + j]);

#pragma unroll
    for (int i = 0; i < 4; i++) {
        int row = r0 + ty * 4 + i;
        if (row < NN) {
            float4 o0, o1;
            o0.x = fmaxf(acc[i][0] + bias[0], 0.f);
            o0.y = fmaxf(acc[i][1] + bias[1], 0.f);
            o0.z = fmaxf(acc[i][2] + bias[2], 0.f);
            o0.w = fmaxf(acc[i][3] + bias[3], 0.f);
            o1.x = fmaxf(acc[i][4] + bias[4], 0.f);
            o1.y = fmaxf(acc[i][5] + bias[5], 0.f);
            o1.z = fmaxf(acc[i][6] + bias[6], 0.f);
            o1.w = fmaxf(acc[i][7] + bias[7], 0.f);
            float* dst = h1 + row * 128 + tx * 8;
            *reinterpret_cast<float4*>(dst) = o0;
            *reinterpret_cast<float4*>(dst + 4) = o1;
        }
    }
}

// ---------------- GEMM2: [hr | h2pre] = h1 @ [W2_r | W2_l] -------------------
__global__ __launch_bounds__(256) void gemm2_kernel(
    const float* __restrict__ h1,
    const float* __restrict__ W2l, const float* __restrict__ W2r,
    float* __restrict__ hr, float* __restrict__ h2pre)
{
    extern __shared__ float sm[];
    float* sA = sm;                 // [64][132]
    float* sB = sm + 64 * 132;      // [128][128]
    const int tid = threadIdx.x;
    const int r0 = blockIdx.x * 64;

    for (int f = tid; f < 128 * 128; f += 256) {
        int k = f >> 7, j = f & 127;
        sB[f] = (j < 64) ? __ldg(&W2r[k * 64 + j]) : __ldg(&W2l[k * 64 + (j - 64)]);
    }
    for (int f = tid; f < 64 * 128; f += 256) {
        int r = f >> 7, k = f & 127;
        int row = r0 + r;
        float v = 0.f;
        if (row < NN) v = h1[row * 128 + k];
        sA[r * 132 + k] = v;
    }
    __syncthreads();

    const int tx = tid & 15, ty = tid >> 4;
    float acc[4][8];
#pragma unroll
    for (int i = 0; i < 4; i++)
#pragma unroll
        for (int j = 0; j < 8; j++) acc[i][j] = 0.f;

    const float* pA = sA + (ty * 4) * 132;
    const float* pB = sB + tx * 8;
#pragma unroll 8
    for (int k = 0; k < 128; k++) {
        float av[4];
        av[0] = pA[k];
        av[1] = pA[132 + k];
        av[2] = pA[264 + k];
        av[3] = pA[396 + k];
        float4 bl = *reinterpret_cast<const float4*>(pB + k * 128);
        float4 bh = *reinterpret_cast<const float4*>(pB + k * 128 + 4);
        float bv[8] = {bl.x, bl.y, bl.z, bl.w, bh.x, bh.y, bh.z, bh.w};
#pragma unroll
        for (int i = 0; i < 4; i++)
#pragma unroll
            for (int j = 0; j < 8; j++)
                acc[i][j] += av[i] * bv[j];
    }

    const int col = tx * 8;
#pragma unroll
    for (int i = 0; i < 4; i++) {
        int row = r0 + ty * 4 + i;
        if (row < NN) {
            float4 o0, o1;
            o0.x = acc[i][0]; o0.y = acc[i][1]; o0.z = acc[i][2]; o0.w = acc[i][3];
            o1.x = acc[i][4]; o1.y = acc[i][5]; o1.z = acc[i][6]; o1.w = acc[i][7];
            float* dst;
            if (col < 64) dst = hr + row * 64 + col;
            else          dst = h2pre + row * 64 + (col - 64);
            *reinterpret_cast<float4*>(dst) = o0;
            *reinterpret_cast<float4*>(dst + 4) = o1;
        }
    }
}

// ------- fused: h2 = relu(agg2' + b2 + hr); scores->tanh->logit; block max --
__global__ __launch_bounds__(256) void node_post_kernel(
    const float* __restrict__ agg2, const float* __restrict__ hr,
    const float* __restrict__ x,
    const float* __restrict__ b2, const float* __restrict__ Wa,
    const float* __restrict__ ba, const float* __restrict__ ctx,
    float* __restrict__ h2out, float* __restrict__ wout, float* __restrict__ bmax)
{
    __shared__ float sWa[64 * 32];
    __shared__ float sba[32], sctx[32], sb2[64];
    __shared__ float swmax[8];
    const int tid = threadIdx.x;
    for (int f = tid; f < 2048; f += 256) sWa[f] = __ldg(&Wa[f]);
    if (tid < 32) { sba[tid] = __ldg(&ba[tid]); sctx[tid] = __ldg(&ctx[tid]); }
    if (tid < 64) sb2[tid] = __ldg(&b2[tid]);
    __syncthreads();

    const int w = tid >> 5, lane = tid & 31;
    const int i = blockIdx.x * 8 + w;
    float myw = -INFINITY;
    if (i < NN) {
        float h0 = fmaxf(agg2[i * 64 + lane] + hr[i * 64 + lane] + sb2[lane], 0.f);
        float h1v = fmaxf(agg2[i * 64 + 32 + lane] + hr[i * 64 + 32 + lane] + sb2[32 + lane], 0.f);
        h2out[i * 64 + lane] = h0;
        h2out[i * 64 + 32 + lane] = h1v;
        float acc = 0.f;
#pragma unroll
        for (int k = 0; k < 32; k++)
            acc += __shfl_sync(0xffffffffu, h0, k) * sWa[k * 32 + lane];
#pragma unroll
        for (int k = 0; k < 32; k++)
            acc += __shfl_sync(0xffffffffu, h1v, k) * sWa[(k + 32) * 32 + lane];
        float t = tanhf(acc + sba[lane]) * sctx[lane];
#pragma unroll
        for (int o = 16; o; o >>= 1) t += __shfl_xor_sync(0xffffffffu, t, o);
        t += 0.4f * x[i * 64 + 63];
        if (lane == 0) wout[i] = t;
        myw = t;
    }
    if (lane == 0) swmax[w] = myw;
    __syncthreads();
    if (tid == 0) {
        float m = swmax[0];
#pragma unroll
        for (int q = 1; q < 8; q++) m = fmaxf(m, swmax[q]);
        bmax[blockIdx.x] = m;
    }
}

__global__ __launch_bounds__(1024) void maxred_kernel(
    const float* __restrict__ bmax, int n, float* __restrict__ gM)
{
    __shared__ float sm_[1024];
    const int t = threadIdx.x;
    float m = -INFINITY;
    for (int i = t; i < n; i += 1024) m = fmaxf(m, bmax[i]);
    sm_[t] = m;
    __syncthreads();
    for (int off = 512; off; off >>= 1) {
        if (t < off) sm_[t] = fmaxf(sm_[t], sm_[t + off]);
        __syncthreads();
    }
    if (t == 0) *gM = sm_[0];
}

// ---------------- exp-weighted pooled sum over all nodes ---------------------
__global__ __launch_bounds__(256) void pool_kernel(
    const float* __restrict__ h2, const float* __restrict__ wlog,
    const float* __restrict__ gM, float* __restrict__ gpool, float* __restrict__ gZ)
{
    const float M = *gM;
    const int lane = threadIdx.x & 31, wloc = threadIdx.x >> 5;
    const int gw = (blockIdx.x * blockDim.x + threadIdx.x) >> 5;
    const int stride = (gridDim.x * blockDim.x) >> 5;
    float a0 = 0.f, a1 = 0.f, z = 0.f;
    for (int i = gw; i < NN; i += stride) {
        float e = expf(wlog[i] - M);
        a0 += e * h2[i * 64 + lane];
        a1 += e * h2[i * 64 + 32 + lane];
        if (lane == 0) z += e;
    }
    __shared__ float sf[8][64];
    __shared__ float sz[8];
    sf[wloc][lane] = a0;
    sf[wloc][lane + 32] = a1;
    if (lane == 0) sz[wloc] = z;
    __syncthreads();
    if (threadIdx.x < 64) {
        float s = 0.f;
#pragma unroll
        for (int q = 0; q < 8; q++) s += sf[q][threadIdx.x];
        atomicAdd(&gpool[threadIdx.x], s);
    }
    if (threadIdx.x == 64) {
        float s = 0.f;
#pragma unroll
        for (int q = 0; q < 8; q++) s += sz[q];
        atomicAdd(gZ, s);
    }
}

// ---------------- tiny head: relu(pooled@Wc1+bc1)@Wc2 -> sigmoid ------------
__global__ __launch_bounds__(32) void final_kernel(
    const float* __restrict__ gpool, const float* __restrict__ gZ,
    const float* __restrict__ Wc1, const float* __restrict__ bc1,
    const float* __restrict__ Wc2, const float* __restrict__ bc2,
    float* __restrict__ out)
{
    const int j = threadIdx.x;   // 32 threads
    const float inv = 1.0f / ((float)NN * (*gZ));
    float acc = bc1[j];
    for (int k = 0; k < 64; k++)
        acc += gpool[k] * inv * Wc1[k * 32 + j];
    float zv = fmaxf(acc, 0.f);
    float s = zv * Wc2[j];
#pragma unroll
    for (int o = 16; o; o >>= 1) s += __shfl_xor_sync(0xffffffffu, s, o);
    if (j == 0) out[0] = 1.0f / (1.0f + expf(-(s + bc2[0])));
}

// ---------------- launch ------------------------------------------------------
extern "C" void kernel_launch(void* const* d_in, const int* in_sizes, int n_in,
                              void* d_out, int out_size) {
    const float* x   = (const float*)d_in[0];
    const void*  ei  = d_in[1];
    const float* W1l = (const float*)d_in[2];
    const float* W1r = (const float*)d_in[3];
    const float* b1  = (const float*)d_in[4];
    const float* W2l = (const float*)d_in[5];
    const float* W2r = (const float*)d_in[6];
    const float* b2  = (const float*)d_in[7];
    const float* Wa  = (const float*)d_in[8];
    const float* ba  = (const float*)d_in[9];
    const float* ctx = (const float*)d_in[10];
    const float* Wc1 = (const float*)d_in[11];
    const float* bc1 = (const float*)d_in[12];
    const float* Wc2 = (const float*)d_in[13];
    const float* bc2 = (const float*)d_in[14];
    float* out = (float*)d_out;

    void *ppool, *pz, *pM, *pagg, *ph1, *phr, *ph2pre, *ph2, *pw, *pbmax;
    cudaGetSymbolAddress(&ppool, g_pool);
    cudaGetSymbolAddress(&pz, g_Z);
    cudaGetSymbolAddress(&pM, g_M);
    cudaGetSymbolAddress(&pagg, g_agg);
    cudaGetSymbolAddress(&ph1, g_h1);
    cudaGetSymbolAddress(&phr, g_hr);
    cudaGetSymbolAddress(&ph2pre, g_h2pre);
    cudaGetSymbolAddress(&ph2, g_h2);
    cudaGetSymbolAddress(&pw, g_w);
    cudaGetSymbolAddress(&pbmax, g_bmax);

    cudaFuncSetAttribute(gemm1_kernel, cudaFuncAttributeMaxDynamicSharedMemorySize, SMEM_GEMM);
    cudaFuncSetAttribute(gemm2_kernel, cudaFuncAttributeMaxDynamicSharedMemorySize, SMEM_GEMM);

    // zero scratch (kernel, not memset: graph memset nodes reject __device__ globals)
    init_kernel<<<(NN + 255) / 256, 256>>>();

    // edge_index dtype detect + convert to int32
    detect_kernel<<<1, 32>>>(ei);
    convert_kernel<<<(2 * EE + 255) / 256, 256>>>(ei);

    // CSR build
    hist_kernel<<<(EE + 255) / 256, 256>>>();
    scan_kernel<<<1, 1024>>>();
    scatter_kernel<<<(EE + 255) / 256, 256>>>();

    // agg1 = mean_agg(x)
    agg_kernel<<<(NN * 32 + 255) / 256, 256>>>(x, (float*)pagg);

    // h1 = relu([agg1|x] @ [W1_l;W1_r] + b1)
    gemm1_kernel<<<(NN + 63) / 64, 256, SMEM_GEMM>>>(
        (const float*)pagg, x, W1l, W1r, b1, (float*)ph1);

    // [hr | h2pre] = h1 @ [W2_r | W2_l]
    gemm2_kernel<<<(NN + 63) / 64, 256, SMEM_GEMM>>>(
        (const float*)ph1, W2l, W2r, (float*)phr, (float*)ph2pre);

    // agg2' = mean_agg(h2pre)  (linearity: == mean_agg(h1) @ W2_l)
    agg_kernel<<<(NN * 32 + 255) / 256, 256>>>((const float*)ph2pre, (float*)pagg);

    // h2 = relu(agg2' + b2 + hr); logits
    node_post_kernel<<<(NN + 7) / 8, 256>>>(
        (const float*)pagg, (const float*)phr, x, b2, Wa, ba, ctx,
        (float*)ph2, (float*)pw, (float*)pbmax);

    maxred_kernel<<<1, 1024>>>((const float*)pbmax, (NN + 7) / 8, (float*)pM);

    pool_kernel<<<1024, 256>>>((const float*)ph2, (const float*)pw,
                               (const float*)pM, (float*)ppool, (float*)pz);

    final_kernel<<<1, 32>>>((const float*)ppool, (const float*)pz,
                            Wc1, bc1, Wc2, bc2, out);
}

// round 6
// speedup vs baseline: 1.0607x; 1.0607x over previous
#include <cuda_runtime.h>
#include <cuda_bf16.h>
#include <mma.h>
#include <math.h>
#include <stdint.h>

using namespace nvcuda;

#define NN 100000
#define EE 1600000

// ---------------- device scratch (allocation-free: __device__ globals) ------
__device__ int   g_eidx[2 * EE];
__device__ int   g_is64;
__device__ int   g_deg[NN];
__device__ int   g_off[NN + 1];
__device__ int   g_cursor[NN];
__device__ int   g_srcs[EE];
__device__ float g_agg[NN * 64];
__device__ float g_h1[NN * 128];
__device__ float g_hr[NN * 64];
__device__ float g_h2pre[NN * 64];
__device__ float g_h2[NN * 64];
__device__ float g_w[NN];
__device__ float g_pool[64];
__device__ float g_Z;
// bf16-split transposed weights: B[n][k], hi/lo
__device__ __nv_bfloat16 g_B1h[128 * 128];
__device__ __nv_bfloat16 g_B1l[128 * 128];
__device__ __nv_bfloat16 g_B2h[128 * 128];
__device__ __nv_bfloat16 g_B2l[128 * 128];

// ---------------- zero-init --------------------------------------------------
__global__ __launch_bounds__(256) void init_kernel() {
    int i = blockIdx.x * blockDim.x + threadIdx.x;
    if (i < NN) { g_deg[i] = 0; g_cursor[i] = 0; }
    if (i < 64) g_pool[i] = 0.f;
    if (i == 0) g_Z = 0.f;
}

// ---------------- edge_index dtype detect + convert(+hist) ------------------
__global__ __launch_bounds__(32) void detect_kernel(const void* ei) {
    const long long* p = (const long long*)ei;
    int lane = threadIdx.x;
    long long v = p[lane * 7];
    bool ok = (v >= 0 && v < NN);
    unsigned m = __ballot_sync(0xffffffffu, ok);
    if (lane == 0) g_is64 = (m == 0xffffffffu) ? 1 : 0;
}

__global__ __launch_bounds__(256) void convert_hist_kernel(const void* ei) {
    int e = blockIdx.x * blockDim.x + threadIdx.x;
    if (e >= 2 * EE) return;
    int v;
    if (g_is64) v = (int)((const long long*)ei)[e];
    else        v = ((const int*)ei)[e];
    g_eidx[e] = v;
    if (e >= EE) atomicAdd(&g_deg[v], 1);
}

// ---------------- CSR build --------------------------------------------------
__global__ __launch_bounds__(1024) void scan_kernel() {
    __shared__ int ss[1024];
    const int t = threadIdx.x;
    const int CHUNK = 98;
    int base = t * CHUNK;
    int local = 0;
#pragma unroll 1
    for (int i = 0; i < CHUNK; i++) {
        int idx = base + i;
        if (idx < NN) local += g_deg[idx];
    }
    ss[t] = local;
    __syncthreads();
#pragma unroll 1
    for (int off = 1; off < 1024; off <<= 1) {
        int tmp = (t >= off) ? ss[t - off] : 0;
        __syncthreads();
        ss[t] += tmp;
        __syncthreads();
    }
    int run = (t > 0) ? ss[t - 1] : 0;
#pragma unroll 1
    for (int i = 0; i < CHUNK; i++) {
        int idx = base + i;
        if (idx < NN) {
            g_off[idx] = run;
            run += g_deg[idx];
        }
    }
    if (t == 1023) g_off[NN] = ss[1023];
}

__global__ __launch_bounds__(256) void scatter_kernel() {
    int e = blockIdx.x * blockDim.x + threadIdx.x;
    if (e < EE) {
        int s = g_eidx[e];
        int d = g_eidx[EE + e];
        int pos = g_off[d] + atomicAdd(&g_cursor[d], 1);
        g_srcs[pos] = s;
    }
}

// ---------------- mean aggregation (warp per node) ---------------------------
__global__ __launch_bounds__(256) void agg_kernel(
    const float* __restrict__ feat, float* __restrict__ out)
{
    int w = (blockIdx.x * blockDim.x + threadIdx.x) >> 5;
    int lane = threadIdx.x & 31;
    if (w >= NN) return;
    int beg = g_off[w];
    int d = g_deg[w];
    int end = beg + d;
    const float2* __restrict__ F = reinterpret_cast<const float2*>(feat);
    float ax = 0.f, ay = 0.f;
    int j = beg;
    for (; j + 1 < end; j += 2) {
        int s0 = __ldg(&g_srcs[j]);
        int s1 = __ldg(&g_srcs[j + 1]);
        float2 v0 = F[s0 * 32 + lane];
        float2 v1 = F[s1 * 32 + lane];
        ax += v0.x + v1.x;
        ay += v0.y + v1.y;
    }
    if (j < end) {
        int s = __ldg(&g_srcs[j]);
        float2 v = F[s * 32 + lane];
        ax += v.x; ay += v.y;
    }
    float inv = 1.0f / fmaxf((float)d, 1.0f);
    float2 o; o.x = ax * inv; o.y = ay * inv;
    reinterpret_cast<float2*>(out)[w * 32 + lane] = o;
}

// ---------------- weight prep: transpose + bf16 hi/lo split ------------------
__global__ __launch_bounds__(256) void prep_weights_kernel(
    const float* __restrict__ W1l, const float* __restrict__ W1r,
    const float* __restrict__ W2l, const float* __restrict__ W2r)
{
    int idx = blockIdx.x * blockDim.x + threadIdx.x;
    if (idx >= 128 * 128) return;
    int n = idx >> 7, k = idx & 127;
    float v1 = (k < 64) ? __ldg(&W1l[k * 128 + n]) : __ldg(&W1r[(k - 64) * 128 + n]);
    __nv_bfloat16 h1 = __float2bfloat16(v1);
    g_B1h[idx] = h1;
    g_B1l[idx] = __float2bfloat16(v1 - __bfloat162float(h1));
    float v2 = (n < 64) ? __ldg(&W2r[k * 64 + n]) : __ldg(&W2l[k * 64 + (n - 64)]);
    __nv_bfloat16 h2 = __float2bfloat16(v2);
    g_B2h[idx] = h2;
    g_B2l[idx] = __float2bfloat16(v2 - __bfloat162float(h2));
}

// ---------------- wmma bf16-split GEMM: 128x128x128 tile per block ----------
// MODE 0: A=[agg|x], out0 = relu(acc + bias) -> h1 (stride 128)
// MODE 1: A=h1, out0 = acc[:, :64] -> hr, out1 = acc[:, 64:] -> h2pre
// smem: sAh[0,32K) sAl[32K,64K) sBh[64K,96K) sBl[96K,128K); epi sC reuses [0,68K)
#define SMEM_WM 131072
#define NTILES ((NN + 127) / 128)

template <int MODE>
__global__ __launch_bounds__(256) void gemm_wmma_kernel(
    const float* __restrict__ A0, const float* __restrict__ A1,
    const __nv_bfloat16* __restrict__ Bh, const __nv_bfloat16* __restrict__ Bl,
    const float* __restrict__ bias,
    float* __restrict__ out0, float* __restrict__ out1)
{
    extern __shared__ char smem[];
    __nv_bfloat16* sAh = (__nv_bfloat16*)(smem);
    __nv_bfloat16* sAl = (__nv_bfloat16*)(smem + 32768);
    __nv_bfloat16* sBh = (__nv_bfloat16*)(smem + 65536);
    __nv_bfloat16* sBl = (__nv_bfloat16*)(smem + 98304);
    float* sC = (float*)smem;                    // [128][132] epilogue buffer

    const int tid = threadIdx.x;
    const int row0 = blockIdx.x * 128;

    // ---- load B (hi/lo), [n][k] layout, 8192 u32 each ----
    {
        const uint32_t* bh = (const uint32_t*)Bh;
        const uint32_t* bl = (const uint32_t*)Bl;
        uint32_t* dh = (uint32_t*)sBh;
        uint32_t* dl = (uint32_t*)sBl;
#pragma unroll 8
        for (int i = tid; i < 8192; i += 256) {
            dh[i] = __ldg(&bh[i]);
            dl[i] = __ldg(&bl[i]);
        }
    }
    // ---- load A rows, split fp32 -> bf16 hi/lo ----
#pragma unroll 4
    for (int i = tid; i < 4096; i += 256) {
        int row = i >> 5;
        int c4 = (i & 31) * 4;
        int grow = row0 + row;
        float4 v = make_float4(0.f, 0.f, 0.f, 0.f);
        if (grow < NN) {
            if (MODE == 0)
                v = (c4 < 64) ? __ldg((const float4*)(A0 + (size_t)grow * 64 + c4))
                              : __ldg((const float4*)(A1 + (size_t)grow * 64 + c4 - 64));
            else
                v = __ldg((const float4*)(A0 + (size_t)grow * 128 + c4));
        }
        __nv_bfloat162 h01 = __floats2bfloat162_rn(v.x, v.y);
        __nv_bfloat162 h23 = __floats2bfloat162_rn(v.z, v.w);
        __nv_bfloat162 l01 = __floats2bfloat162_rn(
            v.x - __bfloat162float(h01.x), v.y - __bfloat162float(h01.y));
        __nv_bfloat162 l23 = __floats2bfloat162_rn(
            v.z - __bfloat162float(h23.x), v.w - __bfloat162float(h23.y));
        uint2 hp, lp;
        hp.x = *(uint32_t*)&h01; hp.y = *(uint32_t*)&h23;
        lp.x = *(uint32_t*)&l01; lp.y = *(uint32_t*)&l23;
        *(uint2*)(sAh + row * 128 + c4) = hp;
        *(uint2*)(sAl + row * 128 + c4) = lp;
    }
    __syncthreads();

    // ---- warp tiling: 8 warps as 4(M) x 2(N); warp tile 32x64 ----
    const int wid = tid >> 5;
    const int wm = wid >> 1;       // 0..3 -> rows wm*32
    const int wn = wid & 1;        // 0..1 -> cols wn*64

    wmma::fragment<wmma::accumulator, 16, 16, 16, float> c[2][4];
#pragma unroll
    for (int i = 0; i < 2; i++)
#pragma unroll
        for (int j = 0; j < 4; j++) wmma::fill_fragment(c[i][j], 0.f);

#pragma unroll 1
    for (int pass = 0; pass < 3; pass++) {
        const __nv_bfloat16* pa = (pass == 2) ? sAl : sAh;
        const __nv_bfloat16* pb = (pass == 1) ? sBl : sBh;
#pragma unroll
        for (int kk = 0; kk < 128; kk += 16) {
            wmma::fragment<wmma::matrix_a, 16, 16, 16, __nv_bfloat16, wmma::row_major> a[2];
            wmma::fragment<wmma::matrix_b, 16, 16, 16, __nv_bfloat16, wmma::col_major> b[4];
#pragma unroll
            for (int i = 0; i < 2; i++)
                wmma::load_matrix_sync(a[i], pa + (wm * 32 + i * 16) * 128 + kk, 128);
#pragma unroll
            for (int j = 0; j < 4; j++)
                wmma::load_matrix_sync(b[j], pb + (wn * 64 + j * 16) * 128 + kk, 128);
#pragma unroll
            for (int i = 0; i < 2; i++)
#pragma unroll
                for (int j = 0; j < 4; j++)
                    wmma::mma_sync(c[i][j], a[i], b[j], c[i][j]);
        }
    }
    __syncthreads();   // A/B dead; reuse smem as sC

    // ---- epilogue: frags -> smem -> fused transform -> global ----
#pragma unroll
    for (int i = 0; i < 2; i++)
#pragma unroll
        for (int j = 0; j < 4; j++)
            wmma::store_matrix_sync(&sC[(wm * 32 + i * 16) * 132 + wn * 64 + j * 16],
                                    c[i][j], 132, wmma::mem_row_major);
    __syncthreads();

#pragma unroll 4
    for (int i = tid; i < 4096; i += 256) {
        int row = i >> 5;
        int c4 = (i & 31) * 4;
        int grow = row0 + row;
        if (grow >= NN) continue;
        float4 o;
        o.x = sC[row * 132 + c4];
        o.y = sC[row * 132 + c4 + 1];
        o.z = sC[row * 132 + c4 + 2];
        o.w = sC[row * 132 + c4 + 3];
        if (MODE == 0) {
            o.x = fmaxf(o.x + __ldg(&bias[c4]), 0.f);
            o.y = fmaxf(o.y + __ldg(&bias[c4 + 1]), 0.f);
            o.z = fmaxf(o.z + __ldg(&bias[c4 + 2]), 0.f);
            o.w = fmaxf(o.w + __ldg(&bias[c4 + 3]), 0.f);
            *(float4*)(out0 + (size_t)grow * 128 + c4) = o;
        } else {
            if (c4 < 64) *(float4*)(out0 + (size_t)grow * 64 + c4) = o;
            else         *(float4*)(out1 + (size_t)grow * 64 + c4 - 64) = o;
        }
    }
}

// ------- fused: h2 = relu(agg2' + b2 + hr); tanh-scores; exp(logit) ---------
__global__ __launch_bounds__(256) void node_post_kernel(
    const float* __restrict__ agg2, const float* __restrict__ hr,
    const float* __restrict__ x,
    const float* __restrict__ b2, const float* __restrict__ Wa,
    const float* __restrict__ ba, const float* __restrict__ ctx,
    float* __restrict__ h2out, float* __restrict__ wout)
{
    __shared__ float sWa[64 * 32];
    __shared__ float sba[32], sctx[32], sb2[64];
    const int tid = threadIdx.x;
    for (int f = tid; f < 2048; f += 256) sWa[f] = __ldg(&Wa[f]);
    if (tid < 32) { sba[tid] = __ldg(&ba[tid]); sctx[tid] = __ldg(&ctx[tid]); }
    if (tid < 64) sb2[tid] = __ldg(&b2[tid]);
    __syncthreads();

    const int w = tid >> 5, lane = tid & 31;
    const int i = blockIdx.x * 8 + w;
    if (i >= NN) return;
    float h0 = fmaxf(agg2[i * 64 + lane] + hr[i * 64 + lane] + sb2[lane], 0.f);
    float h1v = fmaxf(agg2[i * 64 + 32 + lane] + hr[i * 64 + 32 + lane] + sb2[32 + lane], 0.f);
    h2out[i * 64 + lane] = h0;
    h2out[i * 64 + 32 + lane] = h1v;
    float acc = 0.f;
#pragma unroll
    for (int k = 0; k < 32; k++)
        acc += __shfl_sync(0xffffffffu, h0, k) * sWa[k * 32 + lane];
#pragma unroll
    for (int k = 0; k < 32; k++)
        acc += __shfl_sync(0xffffffffu, h1v, k) * sWa[(k + 32) * 32 + lane];
    float t = tanhf(acc + sba[lane]) * sctx[lane];
#pragma unroll
    for (int o = 16; o; o >>= 1) t += __shfl_xor_sync(0xffffffffu, t, o);
    t += 0.4f * x[i * 64 + 63];
    // logits bounded (|t| <= sum|ctx| + 0.4|x| ~ 27): exp safe in fp32, no max pass
    if (lane == 0) wout[i] = expf(t);
}

// ---------------- exp-weighted pooled sum over all nodes ---------------------
__global__ __launch_bounds__(256) void pool_kernel(
    const float* __restrict__ h2, const float* __restrict__ wexp,
    float* __restrict__ gpool, float* __restrict__ gZ)
{
    const int lane = threadIdx.x & 31, wloc = threadIdx.x >> 5;
    const int gw = (blockIdx.x * blockDim.x + threadIdx.x) >> 5;
    const int stride = (gridDim.x * blockDim.x) >> 5;
    float a0 = 0.f, a1 = 0.f, z = 0.f;
    for (int i = gw; i < NN; i += stride) {
        float e = wexp[i];
        a0 += e * h2[i * 64 + lane];
        a1 += e * h2[i * 64 + 32 + lane];
        if (lane == 0) z += e;
    }
    __shared__ float sf[8][64];
    __shared__ float sz[8];
    sf[wloc][lane] = a0;
    sf[wloc][lane + 32] = a1;
    if (lane == 0) sz[wloc] = z;
    __syncthreads();
    if (threadIdx.x < 64) {
        float s = 0.f;
#pragma unroll
        for (int q = 0; q < 8; q++) s += sf[q][threadIdx.x];
        atomicAdd(&gpool[threadIdx.x], s);
    }
    if (threadIdx.x == 64) {
        float s = 0.f;
#pragma unroll
        for (int q = 0; q < 8; q++) s += sz[q];
        atomicAdd(gZ, s);
    }
}

// ---------------- tiny head --------------------------------------------------
__global__ __launch_bounds__(32) void final_kernel(
    const float* __restrict__ gpool, const float* __restrict__ gZ,
    const float* __restrict__ Wc1, const float* __restrict__ bc1,
    const float* __restrict__ Wc2, const float* __restrict__ bc2,
    float* __restrict__ out)
{
    const int j = threadIdx.x;
    const float inv = 1.0f / ((float)NN * (*gZ));
    float acc = bc1[j];
    for (int k = 0; k < 64; k++)
        acc += gpool[k] * inv * Wc1[k * 32 + j];
    float zv = fmaxf(acc, 0.f);
    float s = zv * Wc2[j];
#pragma unroll
    for (int o = 16; o; o >>= 1) s += __shfl_xor_sync(0xffffffffu, s, o);
    if (j == 0) out[0] = 1.0f / (1.0f + expf(-(s + bc2[0])));
}

// ---------------- launch ------------------------------------------------------
extern "C" void kernel_launch(void* const* d_in, const int* in_sizes, int n_in,
                              void* d_out, int out_size) {
    const float* x   = (const float*)d_in[0];
    const void*  ei  = d_in[1];
    const float* W1l = (const float*)d_in[2];
    const float* W1r = (const float*)d_in[3];
    const float* b1  = (const float*)d_in[4];
    const float* W2l = (const float*)d_in[5];
    const float* W2r = (const float*)d_in[6];
    const float* b2  = (const float*)d_in[7];
    const float* Wa  = (const float*)d_in[8];
    const float* ba  = (const float*)d_in[9];
    const float* ctx = (const float*)d_in[10];
    const float* Wc1 = (const float*)d_in[11];
    const float* bc1 = (const float*)d_in[12];
    const float* Wc2 = (const float*)d_in[13];
    const float* bc2 = (const float*)d_in[14];
    float* out = (float*)d_out;

    void *ppool, *pz, *pagg, *ph1, *phr, *ph2pre, *ph2, *pw;
    void *pB1h, *pB1l, *pB2h, *pB2l;
    cudaGetSymbolAddress(&ppool, g_pool);
    cudaGetSymbolAddress(&pz, g_Z);
    cudaGetSymbolAddress(&pagg, g_agg);
    cudaGetSymbolAddress(&ph1, g_h1);
    cudaGetSymbolAddress(&phr, g_hr);
    cudaGetSymbolAddress(&ph2pre, g_h2pre);
    cudaGetSymbolAddress(&ph2, g_h2);
    cudaGetSymbolAddress(&pw, g_w);
    cudaGetSymbolAddress(&pB1h, g_B1h);
    cudaGetSymbolAddress(&pB1l, g_B1l);
    cudaGetSymbolAddress(&pB2h, g_B2h);
    cudaGetSymbolAddress(&pB2l, g_B2l);

    cudaFuncSetAttribute(gemm_wmma_kernel<0>, cudaFuncAttributeMaxDynamicSharedMemorySize, SMEM_WM);
    cudaFuncSetAttribute(gemm_wmma_kernel<1>, cudaFuncAttributeMaxDynamicSharedMemorySize, SMEM_WM);

    init_kernel<<<(NN + 255) / 256, 256>>>();
    detect_kernel<<<1, 32>>>(ei);
    convert_hist_kernel<<<(2 * EE + 255) / 256, 256>>>(ei);
    scan_kernel<<<1, 1024>>>();
    scatter_kernel<<<(EE + 255) / 256, 256>>>();

    prep_weights_kernel<<<64, 256>>>(W1l, W1r, W2l, W2r);

    // agg1 = mean_agg(x)
    agg_kernel<<<(NN * 32 + 255) / 256, 256>>>(x, (float*)pagg);

    // h1 = relu([agg1|x] @ [W1_l;W1_r] + b1)   (wmma bf16-split)
    gemm_wmma_kernel<0><<<NTILES, 256, SMEM_WM>>>(
        (const float*)pagg, x,
        (const __nv_bfloat16*)pB1h, (const __nv_bfloat16*)pB1l,
        b1, (float*)ph1, nullptr);

    // [hr | h2pre] = h1 @ [W2_r | W2_l]
    gemm_wmma_kernel<1><<<NTILES, 256, SMEM_WM>>>(
        (const float*)ph1, nullptr,
        (const __nv_bfloat16*)pB2h, (const __nv_bfloat16*)pB2l,
        nullptr, (float*)phr, (float*)ph2pre);

    // agg2' = mean_agg(h2pre)   (linearity)
    agg_kernel<<<(NN * 32 + 255) / 256, 256>>>((const float*)ph2pre, (float*)pagg);

    node_post_kernel<<<(NN + 7) / 8, 256>>>(
        (const float*)pagg, (const float*)phr, x, b2, Wa, ba, ctx,
        (float*)ph2, (float*)pw);

    pool_kernel<<<1024, 256>>>((const float*)ph2, (const float*)pw,
                               (float*)ppool, (float*)pz);

    final_kernel<<<1, 32>>>((const float*)ppool, (const float*)pz,
                            Wc1, bc1, Wc2, bc2, out);
}

// round 7
// speedup vs baseline: 1.2661x; 1.1936x over previous
#include <cuda_runtime.h>
#include <cuda_bf16.h>
#include <mma.h>
#include <math.h>
#include <stdint.h>

using namespace nvcuda;

#define NN 100000
#define EE 1600000
#define NB ((NN + 255) / 256)   // 391 scan blocks

// ---------------- device scratch (allocation-free: __device__ globals) ------
__device__ int   g_eidx[2 * EE];
__device__ int   g_is64;
__device__ int   g_deg[NN];
__device__ int   g_off[NN + 1];
__device__ int   g_cursor[NN];
__device__ int   g_srcs[EE];
__device__ int   g_bsum[NB];
__device__ float g_agg[NN * 64];
__device__ float g_h1[NN * 128];
__device__ float g_hr[NN * 64];
__device__ float g_h2pre[NN * 64];
__device__ float g_h2[NN * 64];
__device__ float g_w[NN];
__device__ float g_pool[64];
__device__ float g_Z;
// bf16-split transposed weights: B[n][k], hi/lo
__device__ __nv_bfloat16 g_B1h[128 * 128];
__device__ __nv_bfloat16 g_B1l[128 * 128];
__device__ __nv_bfloat16 g_B2h[128 * 128];
__device__ __nv_bfloat16 g_B2l[128 * 128];

// ---------------- zero-init --------------------------------------------------
__global__ __launch_bounds__(256) void init_kernel() {
    int i = blockIdx.x * blockDim.x + threadIdx.x;
    if (i < NN) { g_deg[i] = 0; g_cursor[i] = 0; }
    if (i < 64) g_pool[i] = 0.f;
    if (i == 0) g_Z = 0.f;
}

// ---------------- edge_index dtype detect + convert(+hist) ------------------
__global__ __launch_bounds__(32) void detect_kernel(const void* ei) {
    const long long* p = (const long long*)ei;
    int lane = threadIdx.x;
    long long v = p[lane * 7];
    bool ok = (v >= 0 && v < NN);
    unsigned m = __ballot_sync(0xffffffffu, ok);
    if (lane == 0) g_is64 = (m == 0xffffffffu) ? 1 : 0;
}

__global__ __launch_bounds__(256) void convert_hist_kernel(const void* ei) {
    int e = blockIdx.x * blockDim.x + threadIdx.x;
    if (e >= 2 * EE) return;
    int v;
    if (g_is64) v = (int)((const long long*)ei)[e];
    else        v = ((const int*)ei)[e];
    g_eidx[e] = v;
    if (e >= EE) atomicAdd(&g_deg[v], 1);
}

// ---------------- CSR offsets: 3-phase parallel scan -------------------------
__global__ __launch_bounds__(256) void bsum_kernel() {
    __shared__ int sw[8];
    int i = blockIdx.x * 256 + threadIdx.x;
    int v = (i < NN) ? g_deg[i] : 0;
#pragma unroll
    for (int o = 16; o; o >>= 1) v += __shfl_down_sync(0xffffffffu, v, o);
    if ((threadIdx.x & 31) == 0) sw[threadIdx.x >> 5] = v;
    __syncthreads();
    if (threadIdx.x == 0) {
        int s = 0;
#pragma unroll
        for (int q = 0; q < 8; q++) s += sw[q];
        g_bsum[blockIdx.x] = s;
    }
}

__global__ __launch_bounds__(512) void bscan_kernel() {
    __shared__ int ss[512];
    const int t = threadIdx.x;
    int v = (t < NB) ? g_bsum[t] : 0;
    ss[t] = v;
    __syncthreads();
#pragma unroll 1
    for (int off = 1; off < 512; off <<= 1) {
        int tmp = (t >= off) ? ss[t - off] : 0;
        __syncthreads();
        ss[t] += tmp;
        __syncthreads();
    }
    // exclusive offsets back into g_bsum
    if (t < NB) g_bsum[t] = (t > 0) ? ss[t - 1] : 0;
    if (t == 0) g_off[NN] = ss[NB - 1];
}

__global__ __launch_bounds__(256) void offsets_kernel() {
    __shared__ int sw[8];
    const int t = threadIdx.x;
    const int lane = t & 31, w = t >> 5;
    int i = blockIdx.x * 256 + t;
    int v = (i < NN) ? g_deg[i] : 0;
    // warp inclusive scan
    int sc = v;
#pragma unroll
    for (int o = 1; o < 32; o <<= 1) {
        int n = __shfl_up_sync(0xffffffffu, sc, o);
        if (lane >= o) sc += n;
    }
    if (lane == 31) sw[w] = sc;
    __syncthreads();
    if (t < 8) {
        int a = sw[t];
#pragma unroll
        for (int o = 1; o < 8; o <<= 1) {
            int n = __shfl_up_sync(0x000000ffu, a, o);
            if (t >= o) a += n;
        }
        sw[t] = a;
    }
    __syncthreads();
    int base = g_bsum[blockIdx.x] + ((w > 0) ? sw[w - 1] : 0);
    if (i < NN) g_off[i] = base + sc - v;   // exclusive
}

__global__ __launch_bounds__(256) void scatter_kernel() {
    int e = blockIdx.x * blockDim.x + threadIdx.x;
    if (e < EE) {
        int s = g_eidx[e];
        int d = g_eidx[EE + e];
        int pos = g_off[d] + atomicAdd(&g_cursor[d], 1);
        g_srcs[pos] = s;
    }
}

// ---------------- mean aggregation (warp per node) ---------------------------
__global__ __launch_bounds__(256) void agg_kernel(
    const float* __restrict__ feat, float* __restrict__ out)
{
    int w = (blockIdx.x * blockDim.x + threadIdx.x) >> 5;
    int lane = threadIdx.x & 31;
    if (w >= NN) return;
    int beg = g_off[w];
    int end = g_off[w + 1];
    int d = end - beg;
    const float2* __restrict__ F = reinterpret_cast<const float2*>(feat);
    float ax = 0.f, ay = 0.f;
    int j = beg;
    for (; j + 1 < end; j += 2) {
        int s0 = __ldg(&g_srcs[j]);
        int s1 = __ldg(&g_srcs[j + 1]);
        float2 v0 = F[s0 * 32 + lane];
        float2 v1 = F[s1 * 32 + lane];
        ax += v0.x + v1.x;
        ay += v0.y + v1.y;
    }
    if (j < end) {
        int s = __ldg(&g_srcs[j]);
        float2 v = F[s * 32 + lane];
        ax += v.x; ay += v.y;
    }
    float inv = 1.0f / fmaxf((float)d, 1.0f);
    float2 o; o.x = ax * inv; o.y = ay * inv;
    reinterpret_cast<float2*>(out)[w * 32 + lane] = o;
}

// ---------------- weight prep: transpose + bf16 hi/lo split ------------------
__global__ __launch_bounds__(256) void prep_weights_kernel(
    const float* __restrict__ W1l, const float* __restrict__ W1r,
    const float* __restrict__ W2l, const float* __restrict__ W2r)
{
    int idx = blockIdx.x * blockDim.x + threadIdx.x;
    if (idx >= 128 * 128) return;
    int n = idx >> 7, k = idx & 127;
    float v1 = (k < 64) ? __ldg(&W1l[k * 128 + n]) : __ldg(&W1r[(k - 64) * 128 + n]);
    __nv_bfloat16 h1 = __float2bfloat16(v1);
    g_B1h[idx] = h1;
    g_B1l[idx] = __float2bfloat16(v1 - __bfloat162float(h1));
    float v2 = (n < 64) ? __ldg(&W2r[k * 64 + n]) : __ldg(&W2l[k * 64 + (n - 64)]);
    __nv_bfloat16 h2 = __float2bfloat16(v2);
    g_B2h[idx] = h2;
    g_B2l[idx] = __float2bfloat16(v2 - __bfloat162float(h2));
}

// ---------------- wmma bf16-split GEMM: 128x128x128 tile per block ----------
#define SMEM_WM 131072
#define NTILES ((NN + 127) / 128)

template <int MODE>
__global__ __launch_bounds__(256) void gemm_wmma_kernel(
    const float* __restrict__ A0, const float* __restrict__ A1,
    const __nv_bfloat16* __restrict__ Bh, const __nv_bfloat16* __restrict__ Bl,
    const float* __restrict__ bias,
    float* __restrict__ out0, float* __restrict__ out1)
{
    extern __shared__ char smem[];
    __nv_bfloat16* sAh = (__nv_bfloat16*)(smem);
    __nv_bfloat16* sAl = (__nv_bfloat16*)(smem + 32768);
    __nv_bfloat16* sBh = (__nv_bfloat16*)(smem + 65536);
    __nv_bfloat16* sBl = (__nv_bfloat16*)(smem + 98304);
    float* sC = (float*)smem;                    // [128][132] epilogue buffer

    const int tid = threadIdx.x;
    const int row0 = blockIdx.x * 128;

    {
        const uint32_t* bh = (const uint32_t*)Bh;
        const uint32_t* bl = (const uint32_t*)Bl;
        uint32_t* dh = (uint32_t*)sBh;
        uint32_t* dl = (uint32_t*)sBl;
#pragma unroll 8
        for (int i = tid; i < 8192; i += 256) {
            dh[i] = __ldg(&bh[i]);
            dl[i] = __ldg(&bl[i]);
        }
    }
#pragma unroll 4
    for (int i = tid; i < 4096; i += 256) {
        int row = i >> 5;
        int c4 = (i & 31) * 4;
        int grow = row0 + row;
        float4 v = make_float4(0.f, 0.f, 0.f, 0.f);
        if (grow < NN) {
            if (MODE == 0)
                v = (c4 < 64) ? __ldg((const float4*)(A0 + (size_t)grow * 64 + c4))
                              : __ldg((const float4*)(A1 + (size_t)grow * 64 + c4 - 64));
            else
                v = __ldg((const float4*)(A0 + (size_t)grow * 128 + c4));
        }
        __nv_bfloat162 h01 = __floats2bfloat162_rn(v.x, v.y);
        __nv_bfloat162 h23 = __floats2bfloat162_rn(v.z, v.w);
        __nv_bfloat162 l01 = __floats2bfloat162_rn(
            v.x - __bfloat162float(h01.x), v.y - __bfloat162float(h01.y));
        __nv_bfloat162 l23 = __floats2bfloat162_rn(
            v.z - __bfloat162float(h23.x), v.w - __bfloat162float(h23.y));
        uint2 hp, lp;
        hp.x = *(uint32_t*)&h01; hp.y = *(uint32_t*)&h23;
        lp.x = *(uint32_t*)&l01; lp.y = *(uint32_t*)&l23;
        *(uint2*)(sAh + row * 128 + c4) = hp;
        *(uint2*)(sAl + row * 128 + c4) = lp;
    }
    __syncthreads();

    const int wid = tid >> 5;
    const int wm = wid >> 1;
    const int wn = wid & 1;

    wmma::fragment<wmma::accumulator, 16, 16, 16, float> c[2][4];
#pragma unroll
    for (int i = 0; i < 2; i++)
#pragma unroll
        for (int j = 0; j < 4; j++) wmma::fill_fragment(c[i][j], 0.f);

#pragma unroll 1
    for (int pass = 0; pass < 3; pass++) {
        const __nv_bfloat16* pa = (pass == 2) ? sAl : sAh;
        const __nv_bfloat16* pb = (pass == 1) ? sBl : sBh;
#pragma unroll
        for (int kk = 0; kk < 128; kk += 16) {
            wmma::fragment<wmma::matrix_a, 16, 16, 16, __nv_bfloat16, wmma::row_major> a[2];
            wmma::fragment<wmma::matrix_b, 16, 16, 16, __nv_bfloat16, wmma::col_major> b[4];
#pragma unroll
            for (int i = 0; i < 2; i++)
                wmma::load_matrix_sync(a[i], pa + (wm * 32 + i * 16) * 128 + kk, 128);
#pragma unroll
            for (int j = 0; j < 4; j++)
                wmma::load_matrix_sync(b[j], pb + (wn * 64 + j * 16) * 128 + kk, 128);
#pragma unroll
            for (int i = 0; i < 2; i++)
#pragma unroll
                for (int j = 0; j < 4; j++)
                    wmma::mma_sync(c[i][j], a[i], b[j], c[i][j]);
        }
    }
    __syncthreads();

#pragma unroll
    for (int i = 0; i < 2; i++)
#pragma unroll
        for (int j = 0; j < 4; j++)
            wmma::store_matrix_sync(&sC[(wm * 32 + i * 16) * 132 + wn * 64 + j * 16],
                                    c[i][j], 132, wmma::mem_row_major);
    __syncthreads();

#pragma unroll 4
    for (int i = tid; i < 4096; i += 256) {
        int row = i >> 5;
        int c4 = (i & 31) * 4;
        int grow = row0 + row;
        if (grow >= NN) continue;
        float4 o;
        o.x = sC[row * 132 + c4];
        o.y = sC[row * 132 + c4 + 1];
        o.z = sC[row * 132 + c4 + 2];
        o.w = sC[row * 132 + c4 + 3];
        if (MODE == 0) {
            o.x = fmaxf(o.x + __ldg(&bias[c4]), 0.f);
            o.y = fmaxf(o.y + __ldg(&bias[c4 + 1]), 0.f);
            o.z = fmaxf(o.z + __ldg(&bias[c4 + 2]), 0.f);
            o.w = fmaxf(o.w + __ldg(&bias[c4 + 3]), 0.f);
            *(float4*)(out0 + (size_t)grow * 128 + c4) = o;
        } else {
            if (c4 < 64) *(float4*)(out0 + (size_t)grow * 64 + c4) = o;
            else         *(float4*)(out1 + (size_t)grow * 64 + c4 - 64) = o;
        }
    }
}

// ------- fused: h2 = relu(agg2' + b2 + hr); tanh-scores; exp(logit) ---------
__global__ __launch_bounds__(256) void node_post_kernel(
    const float* __restrict__ agg2, const float* __restrict__ hr,
    const float* __restrict__ x,
    const float* __restrict__ b2, const float* __restrict__ Wa,
    const float* __restrict__ ba, const float* __restrict__ ctx,
    float* __restrict__ h2out, float* __restrict__ wout)
{
    __shared__ float sWa[64 * 32];
    __shared__ float sba[32], sctx[32], sb2[64];
    const int tid = threadIdx.x;
    for (int f = tid; f < 2048; f += 256) sWa[f] = __ldg(&Wa[f]);
    if (tid < 32) { sba[tid] = __ldg(&ba[tid]); sctx[tid] = __ldg(&ctx[tid]); }
    if (tid < 64) sb2[tid] = __ldg(&b2[tid]);
    __syncthreads();

    const int w = tid >> 5, lane = tid & 31;
    const int i = blockIdx.x * 8 + w;
    if (i >= NN) return;
    float h0 = fmaxf(agg2[i * 64 + lane] + hr[i * 64 + lane] + sb2[lane], 0.f);
    float h1v = fmaxf(agg2[i * 64 + 32 + lane] + hr[i * 64 + 32 + lane] + sb2[32 + lane], 0.f);
    h2out[i * 64 + lane] = h0;
    h2out[i * 64 + 32 + lane] = h1v;
    float acc = 0.f;
#pragma unroll
    for (int k = 0; k < 32; k++)
        acc += __shfl_sync(0xffffffffu, h0, k) * sWa[k * 32 + lane];
#pragma unroll
    for (int k = 0; k < 32; k++)
        acc += __shfl_sync(0xffffffffu, h1v, k) * sWa[(k + 32) * 32 + lane];
    float t = tanhf(acc + sba[lane]) * sctx[lane];
#pragma unroll
    for (int o = 16; o; o >>= 1) t += __shfl_xor_sync(0xffffffffu, t, o);
    t += 0.4f * x[i * 64 + 63];
    if (lane == 0) wout[i] = expf(t);
}

// ---------------- exp-weighted pooled sum over all nodes ---------------------
__global__ __launch_bounds__(256) void pool_kernel(
    const float* __restrict__ h2, const float* __restrict__ wexp,
    float* __restrict__ gpool, float* __restrict__ gZ)
{
    const int lane = threadIdx.x & 31, wloc = threadIdx.x >> 5;
    const int gw = (blockIdx.x * blockDim.x + threadIdx.x) >> 5;
    const int stride = (gridDim.x * blockDim.x) >> 5;
    float a0 = 0.f, a1 = 0.f, z = 0.f;
    for (int i = gw; i < NN; i += stride) {
        float e = wexp[i];
        a0 += e * h2[i * 64 + lane];
        a1 += e * h2[i * 64 + 32 + lane];
        if (lane == 0) z += e;
    }
    __shared__ float sf[8][64];
    __shared__ float sz[8];
    sf[wloc][lane] = a0;
    sf[wloc][lane + 32] = a1;
    if (lane == 0) sz[wloc] = z;
    __syncthreads();
    if (threadIdx.x < 64) {
        float s = 0.f;
#pragma unroll
        for (int q = 0; q < 8; q++) s += sf[q][threadIdx.x];
        atomicAdd(&gpool[threadIdx.x], s);
    }
    if (threadIdx.x == 64) {
        float s = 0.f;
#pragma unroll
        for (int q = 0; q < 8; q++) s += sz[q];
        atomicAdd(gZ, s);
    }
}

// ---------------- tiny head --------------------------------------------------
__global__ __launch_bounds__(32) void final_kernel(
    const float* __restrict__ gpool, const float* __restrict__ gZ,
    const float* __restrict__ Wc1, const float* __restrict__ bc1,
    const float* __restrict__ Wc2, const float* __restrict__ bc2,
    float* __restrict__ out)
{
    const int j = threadIdx.x;
    const float inv = 1.0f / ((float)NN * (*gZ));
    float acc = bc1[j];
    for (int k = 0; k < 64; k++)
        acc += gpool[k] * inv * Wc1[k * 32 + j];
    float zv = fmaxf(acc, 0.f);
    float s = zv * Wc2[j];
#pragma unroll
    for (int o = 16; o; o >>= 1) s += __shfl_xor_sync(0xffffffffu, s, o);
    if (j == 0) out[0] = 1.0f / (1.0f + expf(-(s + bc2[0])));
}

// ---------------- launch ------------------------------------------------------
extern "C" void kernel_launch(void* const* d_in, const int* in_sizes, int n_in,
                              void* d_out, int out_size) {
    const float* x   = (const float*)d_in[0];
    const void*  ei  = d_in[1];
    const float* W1l = (const float*)d_in[2];
    const float* W1r = (const float*)d_in[3];
    const float* b1  = (const float*)d_in[4];
    const float* W2l = (const float*)d_in[5];
    const float* W2r = (const float*)d_in[6];
    const float* b2  = (const float*)d_in[7];
    const float* Wa  = (const float*)d_in[8];
    const float* ba  = (const float*)d_in[9];
    const float* ctx = (const float*)d_in[10];
    const float* Wc1 = (const float*)d_in[11];
    const float* bc1 = (const float*)d_in[12];
    const float* Wc2 = (const float*)d_in[13];
    const float* bc2 = (const float*)d_in[14];
    float* out = (float*)d_out;

    void *ppool, *pz, *pagg, *ph1, *phr, *ph2pre, *ph2, *pw;
    void *pB1h, *pB1l, *pB2h, *pB2l;
    cudaGetSymbolAddress(&ppool, g_pool);
    cudaGetSymbolAddress(&pz, g_Z);
    cudaGetSymbolAddress(&pagg, g_agg);
    cudaGetSymbolAddress(&ph1, g_h1);
    cudaGetSymbolAddress(&phr, g_hr);
    cudaGetSymbolAddress(&ph2pre, g_h2pre);
    cudaGetSymbolAddress(&ph2, g_h2);
    cudaGetSymbolAddress(&pw, g_w);
    cudaGetSymbolAddress(&pB1h, g_B1h);
    cudaGetSymbolAddress(&pB1l, g_B1l);
    cudaGetSymbolAddress(&pB2h, g_B2h);
    cudaGetSymbolAddress(&pB2l, g_B2l);

    cudaFuncSetAttribute(gemm_wmma_kernel<0>, cudaFuncAttributeMaxDynamicSharedMemorySize, SMEM_WM);
    cudaFuncSetAttribute(gemm_wmma_kernel<1>, cudaFuncAttributeMaxDynamicSharedMemorySize, SMEM_WM);

    init_kernel<<<(NN + 255) / 256, 256>>>();
    detect_kernel<<<1, 32>>>(ei);
    convert_hist_kernel<<<(2 * EE + 255) / 256, 256>>>(ei);

    // parallel CSR offsets (3-phase scan)
    bsum_kernel<<<NB, 256>>>();
    bscan_kernel<<<1, 512>>>();
    offsets_kernel<<<NB, 256>>>();

    scatter_kernel<<<(EE + 255) / 256, 256>>>();

    prep_weights_kernel<<<64, 256>>>(W1l, W1r, W2l, W2r);

    // agg1 = mean_agg(x)
    agg_kernel<<<(NN * 32 + 255) / 256, 256>>>(x, (float*)pagg);

    // h1 = relu([agg1|x] @ [W1_l;W1_r] + b1)
    gemm_wmma_kernel<0><<<NTILES, 256, SMEM_WM>>>(
        (const float*)pagg, x,
        (const __nv_bfloat16*)pB1h, (const __nv_bfloat16*)pB1l,
        b1, (float*)ph1, nullptr);

    // [hr | h2pre] = h1 @ [W2_r | W2_l]
    gemm_wmma_kernel<1><<<NTILES, 256, SMEM_WM>>>(
        (const float*)ph1, nullptr,
        (const __nv_bfloat16*)pB2h, (const __nv_bfloat16*)pB2l,
        nullptr, (float*)phr, (float*)ph2pre);

    // agg2' = mean_agg(h2pre)   (linearity)
    agg_kernel<<<(NN * 32 + 255) / 256, 256>>>((const float*)ph2pre, (float*)pagg);

    node_post_kernel<<<(NN + 7) / 8, 256>>>(
        (const float*)pagg, (const float*)phr, x, b2, Wa, ba, ctx,
        (float*)ph2, (float*)pw);

    pool_kernel<<<1024, 256>>>((const float*)ph2, (const float*)pw,
                               (float*)ppool, (float*)pz);

    final_kernel<<<1, 32>>>((const float*)ppool, (const float*)pz,
                            Wc1, bc1, Wc2, bc2, out);
}

// round 8
// speedup vs baseline: 2.0494x; 1.6186x over previous
#include <cuda_runtime.h>
#include <cuda_bf16.h>
#include <mma.h>
#include <math.h>
#include <stdint.h>

using namespace nvcuda;

#define NN 100000
#define EE 1600000
#define NB ((NN + 255) / 256)   // 391 scan blocks

// ---------------- device scratch (allocation-free: __device__ globals) ------
__device__ int   g_is64;
__device__ int   g_deg[NN];
__device__ int   g_off[NN + 1];
__device__ int   g_srcs[EE];
__device__ int   g_bsum[NB];
__device__ float g_agg[NN * 64];
__device__ float g_h1[NN * 128];
__device__ float g_hr[NN * 64];
__device__ float g_h2pre[NN * 64];
__device__ float g_pool[64];
__device__ float g_Z;
// bf16-split transposed weights: B[n][k], hi/lo
__device__ __nv_bfloat16 g_B1h[128 * 128];
__device__ __nv_bfloat16 g_B1l[128 * 128];
__device__ __nv_bfloat16 g_B2h[128 * 128];
__device__ __nv_bfloat16 g_B2l[128 * 128];

// ---------------- zero-init --------------------------------------------------
__global__ __launch_bounds__(256) void init_kernel() {
    int i = blockIdx.x * blockDim.x + threadIdx.x;
    if (i < NN) g_deg[i] = 0;
    if (i < 64) g_pool[i] = 0.f;
    if (i == 0) g_Z = 0.f;
}

// ---------------- edge_index dtype detection ---------------------------------
__global__ __launch_bounds__(32) void detect_kernel(const void* ei) {
    const long long* p = (const long long*)ei;
    int lane = threadIdx.x;
    long long v = p[lane * 7];
    bool ok = (v >= 0 && v < NN);
    unsigned m = __ballot_sync(0xffffffffu, ok);
    if (lane == 0) g_is64 = (m == 0xffffffffu) ? 1 : 0;
}

// ---------------- histogram of dst (reads edge_index directly) ---------------
__global__ __launch_bounds__(256) void hist_kernel(const void* ei) {
    int e = blockIdx.x * blockDim.x + threadIdx.x;
    if (e >= EE) return;
    int d;
    if (g_is64) d = (int)((const long long*)ei)[EE + e];
    else        d = ((const int*)ei)[EE + e];
    atomicAdd(&g_deg[d], 1);
}

// ---------------- CSR offsets: 3-phase parallel scan -------------------------
__global__ __launch_bounds__(256) void bsum_kernel() {
    __shared__ int sw[8];
    int i = blockIdx.x * 256 + threadIdx.x;
    int v = (i < NN) ? g_deg[i] : 0;
#pragma unroll
    for (int o = 16; o; o >>= 1) v += __shfl_down_sync(0xffffffffu, v, o);
    if ((threadIdx.x & 31) == 0) sw[threadIdx.x >> 5] = v;
    __syncthreads();
    if (threadIdx.x == 0) {
        int s = 0;
#pragma unroll
        for (int q = 0; q < 8; q++) s += sw[q];
        g_bsum[blockIdx.x] = s;
    }
}

__global__ __launch_bounds__(512) void bscan_kernel() {
    __shared__ int ss[512];
    const int t = threadIdx.x;
    int v = (t < NB) ? g_bsum[t] : 0;
    ss[t] = v;
    __syncthreads();
#pragma unroll 1
    for (int off = 1; off < 512; off <<= 1) {
        int tmp = (t >= off) ? ss[t - off] : 0;
        __syncthreads();
        ss[t] += tmp;
        __syncthreads();
    }
    if (t < NB) g_bsum[t] = (t > 0) ? ss[t - 1] : 0;
    if (t == 0) g_off[NN] = ss[NB - 1];
}

__global__ __launch_bounds__(256) void offsets_kernel() {
    __shared__ int sw[8];
    const int t = threadIdx.x;
    const int lane = t & 31, w = t >> 5;
    int i = blockIdx.x * 256 + t;
    int v = (i < NN) ? g_deg[i] : 0;
    int sc = v;
#pragma unroll
    for (int o = 1; o < 32; o <<= 1) {
        int n = __shfl_up_sync(0xffffffffu, sc, o);
        if (lane >= o) sc += n;
    }
    if (lane == 31) sw[w] = sc;
    __syncthreads();
    if (t < 8) {
        int a = sw[t];
#pragma unroll
        for (int o = 1; o < 8; o <<= 1) {
            int n = __shfl_up_sync(0x000000ffu, a, o);
            if (t >= o) a += n;
        }
        sw[t] = a;
    }
    __syncthreads();
    int base = g_bsum[blockIdx.x] + ((w > 0) ? sw[w - 1] : 0);
    if (i < NN) g_off[i] = base + sc - v;   // exclusive start
}

// scatter mutates g_off in place: afterwards g_off[d] = end(d);
// readers use beg = (d>0) ? g_off[d-1] : 0, end = g_off[d].
__global__ __launch_bounds__(256) void scatter_kernel(const void* ei) {
    int e = blockIdx.x * blockDim.x + threadIdx.x;
    if (e >= EE) return;
    int s, d;
    if (g_is64) {
        s = (int)((const long long*)ei)[e];
        d = (int)((const long long*)ei)[EE + e];
    } else {
        s = ((const int*)ei)[e];
        d = ((const int*)ei)[EE + e];
    }
    int pos = atomicAdd(&g_off[d], 1);
    g_srcs[pos] = s;
}

// ---------------- mean aggregation (warp per node, post-scatter offsets) ----
__global__ __launch_bounds__(256) void agg_kernel(
    const float* __restrict__ feat, float* __restrict__ out)
{
    int w = (blockIdx.x * blockDim.x + threadIdx.x) >> 5;
    int lane = threadIdx.x & 31;
    if (w >= NN) return;
    int beg = (w > 0) ? g_off[w - 1] : 0;
    int end = g_off[w];
    int d = end - beg;
    const float2* __restrict__ F = reinterpret_cast<const float2*>(feat);
    float ax = 0.f, ay = 0.f;
    int j = beg;
    for (; j + 1 < end; j += 2) {
        int s0 = __ldg(&g_srcs[j]);
        int s1 = __ldg(&g_srcs[j + 1]);
        float2 v0 = F[s0 * 32 + lane];
        float2 v1 = F[s1 * 32 + lane];
        ax += v0.x + v1.x;
        ay += v0.y + v1.y;
    }
    if (j < end) {
        int s = __ldg(&g_srcs[j]);
        float2 v = F[s * 32 + lane];
        ax += v.x; ay += v.y;
    }
    float inv = 1.0f / fmaxf((float)d, 1.0f);
    float2 o; o.x = ax * inv; o.y = ay * inv;
    reinterpret_cast<float2*>(out)[w * 32 + lane] = o;
}

// ---------------- weight prep: transpose + bf16 hi/lo split ------------------
__global__ __launch_bounds__(256) void prep_weights_kernel(
    const float* __restrict__ W1l, const float* __restrict__ W1r,
    const float* __restrict__ W2l, const float* __restrict__ W2r)
{
    int idx = blockIdx.x * blockDim.x + threadIdx.x;
    if (idx >= 128 * 128) return;
    int n = idx >> 7, k = idx & 127;
    float v1 = (k < 64) ? __ldg(&W1l[k * 128 + n]) : __ldg(&W1r[(k - 64) * 128 + n]);
    __nv_bfloat16 h1 = __float2bfloat16(v1);
    g_B1h[idx] = h1;
    g_B1l[idx] = __float2bfloat16(v1 - __bfloat162float(h1));
    float v2 = (n < 64) ? __ldg(&W2r[k * 64 + n]) : __ldg(&W2l[k * 64 + (n - 64)]);
    __nv_bfloat16 h2 = __float2bfloat16(v2);
    g_B2h[idx] = h2;
    g_B2l[idx] = __float2bfloat16(v2 - __bfloat162float(h2));
}

// ---------------- wmma bf16-split GEMM (ldm=136 padded smem) -----------------
#define LDM 136
#define ABUF (128 * LDM * 2)     // 34816 bytes per buffer
#define SMEM_WM (4 * ABUF)       // 139264
#define NTILES ((NN + 127) / 128)

template <int MODE>
__global__ __launch_bounds__(256) void gemm_wmma_kernel(
    const float* __restrict__ A0, const float* __restrict__ A1,
    const __nv_bfloat16* __restrict__ Bh, const __nv_bfloat16* __restrict__ Bl,
    const float* __restrict__ bias,
    float* __restrict__ out0, float* __restrict__ out1)
{
    extern __shared__ char smem[];
    __nv_bfloat16* sAh = (__nv_bfloat16*)(smem);
    __nv_bfloat16* sAl = (__nv_bfloat16*)(smem + ABUF);
    __nv_bfloat16* sBh = (__nv_bfloat16*)(smem + 2 * ABUF);
    __nv_bfloat16* sBl = (__nv_bfloat16*)(smem + 3 * ABUF);
    float* sC = (float*)smem;                    // [128][132] epilogue buffer

    const int tid = threadIdx.x;
    const int row0 = blockIdx.x * 128;

    // ---- load B (hi/lo) with padded rows ----
    {
        const uint32_t* bh = (const uint32_t*)Bh;
        const uint32_t* bl = (const uint32_t*)Bl;
        uint32_t* dh = (uint32_t*)sBh;
        uint32_t* dl = (uint32_t*)sBl;
#pragma unroll 8
        for (int i = tid; i < 8192; i += 256) {
            int n = i >> 6, c = i & 63;
            dh[n * (LDM / 2) + c] = __ldg(&bh[i]);
            dl[n * (LDM / 2) + c] = __ldg(&bl[i]);
        }
    }
    // ---- load A rows, split fp32 -> bf16 hi/lo ----
#pragma unroll 4
    for (int i = tid; i < 4096; i += 256) {
        int row = i >> 5;
        int c4 = (i & 31) * 4;
        int grow = row0 + row;
        float4 v = make_float4(0.f, 0.f, 0.f, 0.f);
        if (grow < NN) {
            if (MODE == 0)
                v = (c4 < 64) ? __ldg((const float4*)(A0 + (size_t)grow * 64 + c4))
                              : __ldg((const float4*)(A1 + (size_t)grow * 64 + c4 - 64));
            else
                v = __ldg((const float4*)(A0 + (size_t)grow * 128 + c4));
        }
        __nv_bfloat162 h01 = __floats2bfloat162_rn(v.x, v.y);
        __nv_bfloat162 h23 = __floats2bfloat162_rn(v.z, v.w);
        __nv_bfloat162 l01 = __floats2bfloat162_rn(
            v.x - __bfloat162float(h01.x), v.y - __bfloat162float(h01.y));
        __nv_bfloat162 l23 = __floats2bfloat162_rn(
            v.z - __bfloat162float(h23.x), v.w - __bfloat162float(h23.y));
        uint2 hp, lp;
        hp.x = *(uint32_t*)&h01; hp.y = *(uint32_t*)&h23;
        lp.x = *(uint32_t*)&l01; lp.y = *(uint32_t*)&l23;
        *(uint2*)(sAh + row * LDM + c4) = hp;
        *(uint2*)(sAl + row * LDM + c4) = lp;
    }
    __syncthreads();

    const int wid = tid >> 5;
    const int wm = wid >> 1;
    const int wn = wid & 1;

    wmma::fragment<wmma::accumulator, 16, 16, 16, float> c[2][4];
#pragma unroll
    for (int i = 0; i < 2; i++)
#pragma unroll
        for (int j = 0; j < 4; j++) wmma::fill_fragment(c[i][j], 0.f);

#pragma unroll 1
    for (int pass = 0; pass < 3; pass++) {
        const __nv_bfloat16* pa = (pass == 2) ? sAl : sAh;
        const __nv_bfloat16* pb = (pass == 1) ? sBl : sBh;
#pragma unroll
        for (int kk = 0; kk < 128; kk += 16) {
            wmma::fragment<wmma::matrix_a, 16, 16, 16, __nv_bfloat16, wmma::row_major> a[2];
            wmma::fragment<wmma::matrix_b, 16, 16, 16, __nv_bfloat16, wmma::col_major> b[4];
#pragma unroll
            for (int i = 0; i < 2; i++)
                wmma::load_matrix_sync(a[i], pa + (wm * 32 + i * 16) * LDM + kk, LDM);
#pragma unroll
            for (int j = 0; j < 4; j++)
                wmma::load_matrix_sync(b[j], pb + (wn * 64 + j * 16) * LDM + kk, LDM);
#pragma unroll
            for (int i = 0; i < 2; i++)
#pragma unroll
                for (int j = 0; j < 4; j++)
                    wmma::mma_sync(c[i][j], a[i], b[j], c[i][j]);
        }
    }
    __syncthreads();

#pragma unroll
    for (int i = 0; i < 2; i++)
#pragma unroll
        for (int j = 0; j < 4; j++)
            wmma::store_matrix_sync(&sC[(wm * 32 + i * 16) * 132 + wn * 64 + j * 16],
                                    c[i][j], 132, wmma::mem_row_major);
    __syncthreads();

#pragma unroll 4
    for (int i = tid; i < 4096; i += 256) {
        int row = i >> 5;
        int c4 = (i & 31) * 4;
        int grow = row0 + row;
        if (grow >= NN) continue;
        float4 o;
        o.x = sC[row * 132 + c4];
        o.y = sC[row * 132 + c4 + 1];
        o.z = sC[row * 132 + c4 + 2];
        o.w = sC[row * 132 + c4 + 3];
        if (MODE == 0) {
            o.x = fmaxf(o.x + __ldg(&bias[c4]), 0.f);
            o.y = fmaxf(o.y + __ldg(&bias[c4 + 1]), 0.f);
            o.z = fmaxf(o.z + __ldg(&bias[c4 + 2]), 0.f);
            o.w = fmaxf(o.w + __ldg(&bias[c4 + 3]), 0.f);
            *(float4*)(out0 + (size_t)grow * 128 + c4) = o;
        } else {
            if (c4 < 64) *(float4*)(out0 + (size_t)grow * 64 + c4) = o;
            else         *(float4*)(out1 + (size_t)grow * 64 + c4 - 64) = o;
        }
    }
}

// ------- fused: agg2 gather + h2 + attention + exp + weighted pooling -------
// warp per node; lane holds dims (2*lane, 2*lane+1)
__global__ __launch_bounds__(256) void post_fused_kernel(
    const float* __restrict__ h2pre, const float* __restrict__ hr,
    const float* __restrict__ x,
    const float* __restrict__ b2, const float* __restrict__ Wa,
    const float* __restrict__ ba, const float* __restrict__ ctx,
    float* __restrict__ gpool, float* __restrict__ gZ)
{
    __shared__ float sWa[64 * 32];
    __shared__ float sba[32], sctx[32];
    __shared__ float sb2[64];
    __shared__ float spool[64];
    __shared__ float sZ;
    const int tid = threadIdx.x;
    for (int f = tid; f < 2048; f += 256) sWa[f] = __ldg(&Wa[f]);
    if (tid < 32) { sba[tid] = __ldg(&ba[tid]); sctx[tid] = __ldg(&ctx[tid]); }
    if (tid < 64) { sb2[tid] = __ldg(&b2[tid]); spool[tid] = 0.f; }
    if (tid == 64) sZ = 0.f;
    __syncthreads();

    const int w = tid >> 5, lane = tid & 31;
    const int i = blockIdx.x * 8 + w;
    if (i < NN) {
        // gather: mean over neighbors of h2pre
        int beg = (i > 0) ? g_off[i - 1] : 0;
        int end = g_off[i];
        int d = end - beg;
        const float2* __restrict__ F = reinterpret_cast<const float2*>(h2pre);
        float ax = 0.f, ay = 0.f;
        int j = beg;
        for (; j + 1 < end; j += 2) {
            int s0 = __ldg(&g_srcs[j]);
            int s1 = __ldg(&g_srcs[j + 1]);
            float2 v0 = F[s0 * 32 + lane];
            float2 v1 = F[s1 * 32 + lane];
            ax += v0.x + v1.x;
            ay += v0.y + v1.y;
        }
        if (j < end) {
            int s = __ldg(&g_srcs[j]);
            float2 v = F[s * 32 + lane];
            ax += v.x; ay += v.y;
        }
        float inv = 1.0f / fmaxf((float)d, 1.0f);
        float2 hrv = reinterpret_cast<const float2*>(hr)[i * 32 + lane];
        float v0 = fmaxf(ax * inv + hrv.x + sb2[2 * lane], 0.f);       // dim 2*lane
        float v1 = fmaxf(ay * inv + hrv.y + sb2[2 * lane + 1], 0.f);   // dim 2*lane+1

        // attention: acc_j = sum_k h[k] * Wa[k][j]
        float acc = 0.f;
#pragma unroll
        for (int k = 0; k < 32; k++) {
            float hk0 = __shfl_sync(0xffffffffu, v0, k);
            float hk1 = __shfl_sync(0xffffffffu, v1, k);
            acc += hk0 * sWa[(2 * k) * 32 + lane] + hk1 * sWa[(2 * k + 1) * 32 + lane];
        }
        float t = tanhf(acc + sba[lane]) * sctx[lane];
#pragma unroll
        for (int o = 16; o; o >>= 1) t += __shfl_xor_sync(0xffffffffu, t, o);
        t += 0.4f * __ldg(&x[i * 64 + 63]);
        float e = expf(t);     // logits bounded: no max pass needed
        // pool accumulate into block-shared
        atomicAdd(&spool[2 * lane], e * v0);
        atomicAdd(&spool[2 * lane + 1], e * v1);
        if (lane == 0) atomicAdd(&sZ, e);
    }
    __syncthreads();
    if (tid < 64) atomicAdd(&gpool[tid], spool[tid]);
    if (tid == 64) atomicAdd(gZ, sZ);
}

// ---------------- tiny head --------------------------------------------------
__global__ __launch_bounds__(32) void final_kernel(
    const float* __restrict__ gpool, const float* __restrict__ gZ,
    const float* __restrict__ Wc1, const float* __restrict__ bc1,
    const float* __restrict__ Wc2, const float* __restrict__ bc2,
    float* __restrict__ out)
{
    const int j = threadIdx.x;
    const float inv = 1.0f / ((float)NN * (*gZ));
    float acc = bc1[j];
    for (int k = 0; k < 64; k++)
        acc += gpool[k] * inv * Wc1[k * 32 + j];
    float zv = fmaxf(acc, 0.f);
    float s = zv * Wc2[j];
#pragma unroll
    for (int o = 16; o; o >>= 1) s += __shfl_xor_sync(0xffffffffu, s, o);
    if (j == 0) out[0] = 1.0f / (1.0f + expf(-(s + bc2[0])));
}

// ---------------- launch ------------------------------------------------------
extern "C" void kernel_launch(void* const* d_in, const int* in_sizes, int n_in,
                              void* d_out, int out_size) {
    const float* x   = (const float*)d_in[0];
    const void*  ei  = d_in[1];
    const float* W1l = (const float*)d_in[2];
    const float* W1r = (const float*)d_in[3];
    const float* b1  = (const float*)d_in[4];
    const float* W2l = (const float*)d_in[5];
    const float* W2r = (const float*)d_in[6];
    const float* b2  = (const float*)d_in[7];
    const float* Wa  = (const float*)d_in[8];
    const float* ba  = (const float*)d_in[9];
    const float* ctx = (const float*)d_in[10];
    const float* Wc1 = (const float*)d_in[11];
    const float* bc1 = (const float*)d_in[12];
    const float* Wc2 = (const float*)d_in[13];
    const float* bc2 = (const float*)d_in[14];
    float* out = (float*)d_out;

    void *ppool, *pz, *pagg, *ph1, *phr, *ph2pre;
    void *pB1h, *pB1l, *pB2h, *pB2l;
    cudaGetSymbolAddress(&ppool, g_pool);
    cudaGetSymbolAddress(&pz, g_Z);
    cudaGetSymbolAddress(&pagg, g_agg);
    cudaGetSymbolAddress(&ph1, g_h1);
    cudaGetSymbolAddress(&phr, g_hr);
    cudaGetSymbolAddress(&ph2pre, g_h2pre);
    cudaGetSymbolAddress(&pB1h, g_B1h);
    cudaGetSymbolAddress(&pB1l, g_B1l);
    cudaGetSymbolAddress(&pB2h, g_B2h);
    cudaGetSymbolAddress(&pB2l, g_B2l);

    cudaFuncSetAttribute(gemm_wmma_kernel<0>, cudaFuncAttributeMaxDynamicSharedMemorySize, SMEM_WM);
    cudaFuncSetAttribute(gemm_wmma_kernel<1>, cudaFuncAttributeMaxDynamicSharedMemorySize, SMEM_WM);

    init_kernel<<<(NN + 255) / 256, 256>>>();
    detect_kernel<<<1, 32>>>(ei);
    hist_kernel<<<(EE + 255) / 256, 256>>>(ei);

    // parallel CSR offsets (3-phase scan)
    bsum_kernel<<<NB, 256>>>();
    bscan_kernel<<<1, 512>>>();
    offsets_kernel<<<NB, 256>>>();

    scatter_kernel<<<(EE + 255) / 256, 256>>>(ei);   // mutates g_off -> ends

    prep_weights_kernel<<<64, 256>>>(W1l, W1r, W2l, W2r);

    // agg1 = mean_agg(x)
    agg_kernel<<<(NN * 32 + 255) / 256, 256>>>(x, (float*)pagg);

    // h1 = relu([agg1|x] @ [W1_l;W1_r] + b1)
    gemm_wmma_kernel<0><<<NTILES, 256, SMEM_WM>>>(
        (const float*)pagg, x,
        (const __nv_bfloat16*)pB1h, (const __nv_bfloat16*)pB1l,
        b1, (float*)ph1, nullptr);

    // [hr | h2pre] = h1 @ [W2_r | W2_l]
    gemm_wmma_kernel<1><<<NTILES, 256, SMEM_WM>>>(
        (const float*)ph1, nullptr,
        (const __nv_bfloat16*)pB2h, (const __nv_bfloat16*)pB2l,
        nullptr, (float*)phr, (float*)ph2pre);

    // fused: gather(mean h2pre) + h2 + attention + exp + weighted pool
    post_fused_kernel<<<(NN + 7) / 8, 256>>>(
        (const float*)ph2pre, (const float*)phr, x, b2, Wa, ba, ctx,
        (float*)ppool, (float*)pz);

    final_kernel<<<1, 32>>>((const float*)ppool, (const float*)pz,
                            Wc1, bc1, Wc2, bc2, out);
}